// round 15
// baseline (speedup 1.0000x reference)
#include <cuda_runtime.h>
#include <cuda_fp16.h>
#include <cuda_bf16.h>
#include <math.h>

#define BB   16
#define CC   256
#define NN   2048
#define DQKD 64
#define BINS 32

// ---------------- scratch (device globals; no allocation allowed) ----------------
__device__ __half g_q[BB * NN * DQKD];            // [b][n][64] fp16 point-major
__device__ __half g_k[BB * NN * DQKD];            // [b][m][64] fp16 point-major
__device__ __half g_vh[BB * CC * NN];             // [b][c][n] fp16 V
__device__ __nv_bfloat16 g_energy[(size_t)BB * NN * NN]; // [b][n][m] exp(e) bf16
__device__ float  g_rowsuminv[BB * NN];

// ---------------- mma helpers ----------------
__device__ __forceinline__ unsigned packh2(float a, float b)
{
    __half2 h = __floats2half2_rn(a, b);
    return *reinterpret_cast<unsigned*>(&h);
}

__device__ __forceinline__ void mma_f16(float c[4], const unsigned a[4], const unsigned b[2])
{
    asm volatile(
        "mma.sync.aligned.m16n8k16.row.col.f32.f16.f16.f32 "
        "{%0,%1,%2,%3},{%4,%5,%6,%7},{%8,%9},{%0,%1,%2,%3};"
        : "+f"(c[0]), "+f"(c[1]), "+f"(c[2]), "+f"(c[3])
        : "r"(a[0]), "r"(a[1]), "r"(a[2]), "r"(a[3]), "r"(b[0]), "r"(b[1]));
}

__device__ __forceinline__ void ldsm_x4(unsigned r[4], const void* p)
{
    unsigned addr = (unsigned)__cvta_generic_to_shared(p);
    asm volatile("ldmatrix.sync.aligned.m8n8.x4.shared.b16 {%0,%1,%2,%3}, [%4];"
                 : "=r"(r[0]), "=r"(r[1]), "=r"(r[2]), "=r"(r[3]) : "r"(addr));
}

__device__ __forceinline__ void cp_async16(void* smem_dst, const void* gptr)
{
    unsigned dst = (unsigned)__cvta_generic_to_shared(smem_dst);
    asm volatile("cp.async.cg.shared.global [%0], [%1], 16;" :: "r"(dst), "l"(gptr));
}

// ============ fp16 128x128 GEMM chunk helpers (256 threads) ============
#define GEMM128_LOADB(xb)                                                          \
    _Pragma("unroll")                                                              \
    for (int i = 0; i < 2; i++) {                                                  \
        int task = t + i * 256;                                                    \
        int kp = task >> 5, m4 = task & 31;                                        \
        float4 f0 = *reinterpret_cast<const float4*>(&(xb)[(size_t)(k0 + 2 * kp) * NN + m0 + m4 * 4]); \
        float4 f1 = *reinterpret_cast<const float4*>(&(xb)[(size_t)(k0 + 2 * kp + 1) * NN + m0 + m4 * 4]); \
        Bs[kp][m4 * 4 + 0] = packh2(f0.x, f1.x);                                   \
        Bs[kp][m4 * 4 + 1] = packh2(f0.y, f1.y);                                   \
        Bs[kp][m4 * 4 + 2] = packh2(f0.z, f1.z);                                   \
        Bs[kp][m4 * 4 + 3] = packh2(f0.w, f1.w);                                   \
    }

#define GEMM128_MMA()                                                              \
    _Pragma("unroll")                                                              \
    for (int ks = 0; ks < 2; ks++) {                                               \
        unsigned af[4][4], bf[4][2];                                               \
        _Pragma("unroll")                                                          \
        for (int mt = 0; mt < 4; mt++) {                                           \
            int row = wm * 64 + mt * 16 + (lane >> 2);                             \
            int col = ks * 8 + (lane & 3);                                         \
            af[mt][0] = As[row][col];                                              \
            af[mt][1] = As[row + 8][col];                                          \
            af[mt][2] = As[row][col + 4];                                          \
            af[mt][3] = As[row + 8][col + 4];                                      \
        }                                                                          \
        _Pragma("unroll")                                                          \
        for (int nt = 0; nt < 4; nt++) {                                           \
            int kp = ks * 8 + (lane & 3);                                          \
            int cm = wn * 32 + nt * 8 + (lane >> 2);                               \
            bf[nt][0] = Bs[kp][cm];                                                \
            bf[nt][1] = Bs[kp + 4][cm];                                            \
        }                                                                          \
        _Pragma("unroll")                                                          \
        for (int mt = 0; mt < 4; mt++)                                             \
            _Pragma("unroll")                                                      \
            for (int nt = 0; nt < 4; nt++) mma_f16(c[mt][nt], af[mt], bf[nt]);     \
    }

// ---------------- K1: fused projections  q,k,vh  (fp16 MMA) ----------------
// oc=0: [Wq;Wk] -> q,k ; oc=1: Wv[0:128] -> vh ; oc=2: Wv[128:256] -> vh.
__global__ __launch_bounds__(256) void projqkv_f16_kernel(
    const float* __restrict__ Wq, const float* __restrict__ Wk,
    const float* __restrict__ Wv, const float* __restrict__ x,
    const float* __restrict__ bv, __half* __restrict__ qo,
    __half* __restrict__ ko, __half* __restrict__ vh)
{
    __shared__ unsigned As[128][20];
    __shared__ unsigned Bs[16][136];
    int b  = blockIdx.z;
    int m0 = blockIdx.x * 128;
    int t  = threadIdx.x;
    int warp = t >> 5, lane = t & 31;
    int wm = warp >> 2, wn = warp & 3;
    const float* xb = x + (size_t)b * CC * NN;

    for (int oc = 0; oc < 3; oc++) {
        float c[4][4][4] = {};
        for (int k0 = 0; k0 < CC; k0 += 32) {
#pragma unroll
            for (int i = 0; i < 4; i++) {
                int idx = t + i * 256;
                int dd = idx >> 3, kq = idx & 7;
                const float* srcA = (oc == 0)
                    ? ((dd < 64) ? (Wq + (size_t)dd * CC) : (Wk + (size_t)(dd - 64) * CC))
                    : (Wv + (size_t)((oc - 1) * 128 + dd) * CC);
                float4 f = *reinterpret_cast<const float4*>(&srcA[k0 + kq * 4]);
                As[dd][kq * 2 + 0] = packh2(f.x, f.y);
                As[dd][kq * 2 + 1] = packh2(f.z, f.w);
            }
            GEMM128_LOADB(xb)
            __syncthreads();
            GEMM128_MMA()
            __syncthreads();
        }
        if (oc == 0) {
#pragma unroll
            for (int mt = 0; mt < 4; mt++)
#pragma unroll
                for (int h = 0; h < 2; h++) {
                    int o = wm * 64 + mt * 16 + h * 8 + (lane >> 2);
                    __half* dst = (o < 64) ? qo : ko;
                    int oc2 = o & 63;
#pragma unroll
                    for (int nt = 0; nt < 4; nt++) {
                        int n = m0 + wn * 32 + nt * 8 + (lane & 3) * 2;
                        dst[((size_t)b * NN + n) * 64 + oc2]     = __float2half_rn(c[mt][nt][h * 2 + 0]);
                        dst[((size_t)b * NN + n + 1) * 64 + oc2] = __float2half_rn(c[mt][nt][h * 2 + 1]);
                    }
                }
        } else {
#pragma unroll
            for (int mt = 0; mt < 4; mt++)
#pragma unroll
                for (int h = 0; h < 2; h++) {
                    int o = (oc - 1) * 128 + wm * 64 + mt * 16 + h * 8 + (lane >> 2);
                    float bvv = bv[o];
#pragma unroll
                    for (int nt = 0; nt < 4; nt++) {
                        int mm = m0 + wn * 32 + nt * 8 + (lane & 3) * 2;
                        size_t idx = ((size_t)b * CC + o) * NN + mm;
                        __half2 h2 = __floats2half2_rn(c[mt][nt][h * 2 + 0] + bvv,
                                                       c[mt][nt][h * 2 + 1] + bvv);
                        *reinterpret_cast<__half2*>(&vh[idx]) = h2;
                    }
                }
        }
    }
}

// ---------------- K3: energy pass (fp16 MMA, fp16 q/k, ldmatrix A) ------------------
__global__ __launch_bounds__(256, 2) void energy2_kernel(
    const __half* __restrict__ q, const __half* __restrict__ k,
    const float* __restrict__ xlt, const float* __restrict__ ylt,
    const float* __restrict__ zlt, const int* __restrict__ disc,
    __nv_bfloat16* __restrict__ energy, float* __restrict__ rowsuminv)
{
    extern __shared__ unsigned smu[];
    unsigned* Qe = smu;                     // [64][36] u32 (half pairs)
    unsigned* Ks = Qe + 64 * 36;            // [128][36] u32 (half pairs; lt overlay)
    float*    Tw = (float*)(Ks + 128 * 36); // [64][100]
    int*      dn = (int*)(Tw + 64 * 100);   // [192]
    int*      dm = dn + 192;                // [384]
    float*    red = (float*)(dm + 384);     // [256]

    int b  = blockIdx.y;
    int n0 = blockIdx.x * 64;
    int t  = threadIdx.x;
    int warp = t >> 5, lane = t & 31;
    int wr = warp >> 2, wc = warp & 3;

    int lm_row = ((lane >> 3) & 1) * 8 + (lane & 7);
    int lm_k   = (lane >> 4) * 8;

#pragma unroll
    for (int i = 0; i < 2; i++) {
        int idx = t + i * 256;
        int n = idx >> 3, kq = idx & 7;
        uint4 u = *reinterpret_cast<const uint4*>(&q[((size_t)b * NN + n0 + n) * 64 + kq * 8]);
        Qe[n * 36 + kq * 4 + 0] = u.x; Qe[n * 36 + kq * 4 + 1] = u.y;
        Qe[n * 36 + kq * 4 + 2] = u.z; Qe[n * 36 + kq * 4 + 3] = u.w;
    }
    if (t < 192) dn[t] = disc[((size_t)b * NN + n0) * 3 + t];

    uint4 kreg[4];
    int dmreg0, dmreg1;
#pragma unroll
    for (int i = 0; i < 4; i++) {
        int idx = t + i * 256;
        int m = idx >> 3, kq = idx & 7;
        kreg[i] = *reinterpret_cast<const uint4*>(&k[((size_t)b * NN + m) * 64 + kq * 8]);
    }
    dmreg0 = disc[((size_t)b * NN) * 3 + t];
    dmreg1 = (t < 128) ? disc[((size_t)b * NN) * 3 + t + 256] : 0;

    const float* lt_ptrs[3] = {xlt, ylt, zlt};
    unsigned* lts = Ks;
    int qrow0 = (warp & 3) * 16;
    int qcol0 = (warp >> 2) * 32;
    for (int a = 0; a < 3; a++) {
        __syncthreads();
        for (int i = t; i < 64 * 32; i += 256) {
            int r = i >> 5, jp = i & 31;
            float v0 = (r < 63) ? lt_ptrs[a][r * 64 + 2 * jp] : 0.f;
            float v1 = (r < 63) ? lt_ptrs[a][r * 64 + 2 * jp + 1] : 0.f;
            lts[r * 36 + jp] = packh2(v0, v1);
        }
        __syncthreads();
        float c2[4][4] = {};
#pragma unroll
        for (int ks = 0; ks < 4; ks++) {
            unsigned af[4], bf[4][2];
            ldsm_x4(af, (const unsigned short*)Qe + (qrow0 + lm_row) * 72 + ks * 16 + lm_k);
            int col = ks * 8 + (lane & 3);
#pragma unroll
            for (int nt = 0; nt < 4; nt++) {
                int cm = qcol0 + nt * 8 + (lane >> 2);
                bf[nt][0] = lts[cm * 36 + col];
                bf[nt][1] = lts[cm * 36 + col + 4];
            }
#pragma unroll
            for (int nt = 0; nt < 4; nt++) mma_f16(c2[nt], af, bf[nt]);
        }
#pragma unroll
        for (int nt = 0; nt < 4; nt++)
#pragma unroll
            for (int h = 0; h < 2; h++) {
                int row = qrow0 + h * 8 + (lane >> 2);
                int dna = dn[row * 3 + a];
#pragma unroll
                for (int j = 0; j < 2; j++) {
                    int col = qcol0 + nt * 8 + (lane & 3) * 2 + j;
                    int d = col - 31 + dna;
                    if (d >= 0 && d < 32)
                        Tw[row * 100 + a * 32 + d] = c2[nt][h * 2 + j];
                }
            }
    }

    float rsm[2][2] = {};

    for (int m0c = 0; m0c < NN; m0c += 128) {
        __syncthreads();
#pragma unroll
        for (int i = 0; i < 4; i++) {
            int idx = t + i * 256;
            int m = idx >> 3, kq = idx & 7;
            Ks[m * 36 + kq * 4 + 0] = kreg[i].x; Ks[m * 36 + kq * 4 + 1] = kreg[i].y;
            Ks[m * 36 + kq * 4 + 2] = kreg[i].z; Ks[m * 36 + kq * 4 + 3] = kreg[i].w;
        }
        dm[t] = dmreg0;
        if (t < 128) dm[t + 256] = dmreg1;
        __syncthreads();
        if (m0c + 128 < NN) {
#pragma unroll
            for (int i = 0; i < 4; i++) {
                int idx = t + i * 256;
                int m = idx >> 3, kq = idx & 7;
                kreg[i] = *reinterpret_cast<const uint4*>(
                    &k[((size_t)b * NN + m0c + 128 + m) * 64 + kq * 8]);
            }
            dmreg0 = disc[((size_t)b * NN + m0c + 128) * 3 + t];
            dmreg1 = (t < 128) ? disc[((size_t)b * NN + m0c + 128) * 3 + t + 256] : 0;
        }

        float c[2][4][4] = {};
#pragma unroll
        for (int ks = 0; ks < 4; ks++) {
            unsigned af[2][4], bf[4][2];
#pragma unroll
            for (int mt = 0; mt < 2; mt++)
                ldsm_x4(af[mt], (const unsigned short*)Qe
                        + (wr * 32 + mt * 16 + lm_row) * 72 + ks * 16 + lm_k);
            int col = ks * 8 + (lane & 3);
#pragma unroll
            for (int nt = 0; nt < 4; nt++) {
                int cm = wc * 32 + nt * 8 + (lane >> 2);
                bf[nt][0] = Ks[cm * 36 + col];
                bf[nt][1] = Ks[cm * 36 + col + 4];
            }
#pragma unroll
            for (int mt = 0; mt < 2; mt++)
#pragma unroll
                for (int nt = 0; nt < 4; nt++) mma_f16(c[mt][nt], af[mt], bf[nt]);
        }

#pragma unroll
        for (int mt = 0; mt < 2; mt++)
#pragma unroll
            for (int h = 0; h < 2; h++) {
                int row_l = wr * 32 + mt * 16 + h * 8 + (lane >> 2);
                const float* twr = &Tw[row_l * 100];
#pragma unroll
                for (int nt = 0; nt < 4; nt++) {
                    float pv[2];
#pragma unroll
                    for (int j = 0; j < 2; j++) {
                        int col = wc * 32 + nt * 8 + (lane & 3) * 2 + j;
                        float e = c[mt][nt][h * 2 + j]
                                + twr[dm[col * 3 + 0]]
                                + twr[32 + dm[col * 3 + 1]]
                                + twr[64 + dm[col * 3 + 2]];
                        float p = __expf(e);
                        rsm[mt][h] += p;
                        pv[j] = p;
                    }
                    int col0 = wc * 32 + nt * 8 + (lane & 3) * 2;
                    __nv_bfloat162 bp = __floats2bfloat162_rn(pv[0], pv[1]);
                    *reinterpret_cast<__nv_bfloat162*>(
                        &energy[((size_t)b * NN + n0 + row_l) * NN + m0c + col0]) = bp;
                }
            }
    }

#pragma unroll
    for (int mt = 0; mt < 2; mt++)
#pragma unroll
        for (int h = 0; h < 2; h++) {
            float s = rsm[mt][h];
            s += __shfl_xor_sync(0xffffffffu, s, 1);
            s += __shfl_xor_sync(0xffffffffu, s, 2);
            if ((lane & 3) == 0) {
                int row_l = wr * 32 + mt * 16 + h * 8 + (lane >> 2);
                red[wc * 64 + row_l] = s;
            }
        }
    __syncthreads();
    if (t < 64) {
        float s = red[t] + red[64 + t] + red[128 + t] + red[192 + t];
        rowsuminv[b * NN + n0 + t] = 1.f / s;
    }
}

// ---------------- K5: FUSED  out = x + relu(BN(Wt @ (x - V@P/colsum) + bt)) ---------
#define VSTRIDE_H 72   // halves per V row
#define PSTRIDE   132  // u32 (half2) per P kp-row
#define OFF_PB    (2 * 256 * VSTRIDE_H * 2)             // 73728
#define OFF_CSP   (OFF_PB + 2 * 32 * PSTRIDE * 4)       // 107520
#define OFF_CSC   (OFF_CSP + 512 * 8 * 4)               // 123904
#define SMEM_XRF  (OFF_CSC + 128 * 4)                   // 124416
__global__ __launch_bounds__(512) void xrf_kernel(
    const __half* __restrict__ vh, const __nv_bfloat16* __restrict__ energy,
    const float* __restrict__ rowsuminv, const float* __restrict__ x,
    const float* __restrict__ Wt, const float* __restrict__ bt,
    const float* __restrict__ gamma, const float* __restrict__ beta,
    const float* __restrict__ mean, const float* __restrict__ var,
    float* __restrict__ out)
{
    extern __shared__ char smc[];
    __half* Vh = (__half*)smc;
    unsigned* Pb = (unsigned*)(smc + OFF_PB);
    float* csp = (float*)(smc + OFF_CSP);
    float* cscale = (float*)(smc + OFF_CSC);

    int b  = blockIdx.z;
    int m0 = blockIdx.x * 128;
    int t  = threadIdx.x;
    int warp = t >> 5, lane = t & 31;
    int wr = warp >> 2, wc = warp & 3;
    float c[4][4][4] = {};
    float csum[8] = {};
    const __half* vb = vh + (size_t)b * CC * NN;
    const __nv_bfloat16* eb = energy + (size_t)b * NN * NN;
    const float* ri = rowsuminv + b * NN;

    int kp_t = t >> 4;
    int mq8  = t & 15;
    int lm_row = ((lane >> 3) & 1) * 8 + (lane & 7);
    int lm_k   = (lane >> 4) * 8;

#define BF2F_LO(u) __uint_as_float((u) << 16)
#define BF2F_HI(u) __uint_as_float((u) & 0xffff0000u)

#define XR_ELOAD(kb)                                                                \
    r0 = *reinterpret_cast<const uint4*>(&eb[(size_t)((kb) + 2 * kp_t) * NN + m0 + mq8 * 8]); \
    r1 = *reinterpret_cast<const uint4*>(&eb[(size_t)((kb) + 2 * kp_t + 1) * NN + m0 + mq8 * 8]); \
    rv0 = ri[(kb) + 2 * kp_t]; rv1 = ri[(kb) + 2 * kp_t + 1];

#define XR_PSTORE(Pdst)                                                             \
    do {                                                                            \
        unsigned* pd = &(Pdst)[kp_t * PSTRIDE + mq8 * 8];                           \
        const unsigned* w0 = &r0.x; const unsigned* w1 = &r1.x;                     \
        _Pragma("unroll")                                                           \
        for (int w = 0; w < 4; w++) {                                               \
            float a0 = BF2F_LO(w0[w]) * rv0, a1 = BF2F_HI(w0[w]) * rv0;             \
            float b0 = BF2F_LO(w1[w]) * rv1, b1 = BF2F_HI(w1[w]) * rv1;             \
            csum[2 * w + 0] += a0 + b0;                                             \
            csum[2 * w + 1] += a1 + b1;                                             \
            pd[2 * w + 0] = packh2(a0, b0);                                         \
            pd[2 * w + 1] = packh2(a1, b1);                                         \
        }                                                                           \
    } while (0)

    // ---- prologue: chunk 0 ----
    {
        uint4 r0, r1; float rv0, rv1;
#pragma unroll
        for (int i = 0; i < 4; i++) {
            int idx = t + i * 512;
            int dd = idx >> 3, kq = idx & 7;
            cp_async16(&Vh[dd * VSTRIDE_H + kq * 8], &vb[(size_t)dd * NN + kq * 8]);
        }
        asm volatile("cp.async.commit_group;");
        XR_ELOAD(0);
        XR_PSTORE(Pb);
        asm volatile("cp.async.wait_group 0;");
        __syncthreads();
    }

    int cur = 0;
    for (int k0 = 0; k0 < NN; k0 += 64) {
        int nxt = cur ^ 1;
        bool has_next = (k0 + 64) < NN;
        uint4 r0, r1; float rv0, rv1;
        if (has_next) {
            __half* Vn = Vh + nxt * 256 * VSTRIDE_H;
#pragma unroll
            for (int i = 0; i < 4; i++) {
                int idx = t + i * 512;
                int dd = idx >> 3, kq = idx & 7;
                cp_async16(&Vn[dd * VSTRIDE_H + kq * 8], &vb[(size_t)dd * NN + k0 + 64 + kq * 8]);
            }
            asm volatile("cp.async.commit_group;");
            XR_ELOAD(k0 + 64);
        }
        const __half* Vcur = Vh + cur * 256 * VSTRIDE_H;
        const unsigned* Ps = Pb + cur * 32 * PSTRIDE;
#pragma unroll
        for (int ks16 = 0; ks16 < 4; ks16++) {
            unsigned af[4][4], bf[4][2];
#pragma unroll
            for (int mt = 0; mt < 4; mt++)
                ldsm_x4(af[mt], Vcur + (wr * 64 + mt * 16 + lm_row) * VSTRIDE_H
                                + ks16 * 16 + lm_k);
#pragma unroll
            for (int nt = 0; nt < 4; nt++) {
                int cm = wc * 32 + nt * 8 + (lane >> 2);
                int kp = ks16 * 8 + (lane & 3);
                bf[nt][0] = Ps[kp * PSTRIDE + cm];
                bf[nt][1] = Ps[(kp + 4) * PSTRIDE + cm];
            }
#pragma unroll
            for (int mt = 0; mt < 4; mt++)
#pragma unroll
                for (int nt = 0; nt < 4; nt++) mma_f16(c[mt][nt], af[mt], bf[nt]);
        }
        if (has_next) {
            XR_PSTORE(Pb + nxt * 32 * PSTRIDE);
            asm volatile("cp.async.wait_group 0;");
        }
        __syncthreads();
        cur = nxt;
    }

    // ---- colsum reduce ----
#pragma unroll
    for (int j = 0; j < 8; j++) csp[t * 8 + j] = csum[j];
    __syncthreads();
    if (t < 128) {
        int g = t >> 3, j = t & 7;
        float s = 0.f;
#pragma unroll
        for (int kp = 0; kp < 32; kp++) s += csp[(kp * 16 + g) * 8 + j];
        cscale[t] = 1.f / (1e-9f + s);
    }
    __syncthreads();

    // ---- compute xd tile (fp16, k-pair layout) into smem (overlays Vh region) ----
    unsigned short* XDkp16 = (unsigned short*)smc;   // [128 kp][132 m u32] viewed as u16
#pragma unroll
    for (int mt = 0; mt < 4; mt++)
#pragma unroll
        for (int h = 0; h < 2; h++) {
            int dd = wr * 64 + mt * 16 + h * 8 + (lane >> 2);
            int kp = dd >> 1, byt = dd & 1;
#pragma unroll
            for (int nt = 0; nt < 4; nt++) {
                int mloc = wc * 32 + nt * 8 + (lane & 3) * 2;
                float s0 = cscale[mloc], s1 = cscale[mloc + 1];
                size_t idx = ((size_t)b * CC + dd) * NN + m0 + mloc;
                float2 xv = *reinterpret_cast<const float2*>(&x[idx]);
                float xd0 = xv.x - c[mt][nt][h * 2 + 0] * s0;
                float xd1 = xv.y - c[mt][nt][h * 2 + 1] * s1;
                __half h0 = __float2half_rn(xd0);
                __half h1 = __float2half_rn(xd1);
                XDkp16[(kp * PSTRIDE + mloc) * 2 + byt]     = *(unsigned short*)&h0;
                XDkp16[(kp * PSTRIDE + mloc + 1) * 2 + byt] = *(unsigned short*)&h1;
            }
        }
    __syncthreads();

    // ---- in-block final GEMM: out = x + relu(BN(Wt @ xd + bt)) --------------------
    // A = Wt [256 o][256 k] fp32 from global (L2-hot), B = XDkp in smem.
    const unsigned* XDkp = (const unsigned*)smc;     // [128 kp][PSTRIDE]
    unsigned (*As2)[20] = (unsigned(*)[20])(smc + OFF_PB);   // [256][20] (Pb region dead)
#pragma unroll
    for (int mt = 0; mt < 4; mt++)
#pragma unroll
        for (int nt = 0; nt < 4; nt++)
#pragma unroll
            for (int j = 0; j < 4; j++) c[mt][nt][j] = 0.f;

    for (int k0 = 0; k0 < CC; k0 += 32) {
#pragma unroll
        for (int i = 0; i < 4; i++) {
            int idx = t + i * 512;
            int dd = idx >> 3, kq = idx & 7;
            float4 f = *reinterpret_cast<const float4*>(&Wt[(size_t)dd * CC + k0 + kq * 4]);
            As2[dd][kq * 2 + 0] = packh2(f.x, f.y);
            As2[dd][kq * 2 + 1] = packh2(f.z, f.w);
        }
        __syncthreads();
#pragma unroll
        for (int ks = 0; ks < 2; ks++) {
            unsigned af[4][4], bf[4][2];
#pragma unroll
            for (int mt = 0; mt < 4; mt++) {
                int row = wr * 64 + mt * 16 + (lane >> 2);
                int col = ks * 8 + (lane & 3);
                af[mt][0] = As2[row][col];
                af[mt][1] = As2[row + 8][col];
                af[mt][2] = As2[row][col + 4];
                af[mt][3] = As2[row + 8][col + 4];
            }
            int kp = (k0 >> 1) + ks * 8 + (lane & 3);
#pragma unroll
            for (int nt = 0; nt < 4; nt++) {
                int cm = wc * 32 + nt * 8 + (lane >> 2);
                bf[nt][0] = XDkp[kp * PSTRIDE + cm];
                bf[nt][1] = XDkp[(kp + 4) * PSTRIDE + cm];
            }
#pragma unroll
            for (int mt = 0; mt < 4; mt++)
#pragma unroll
                for (int nt = 0; nt < 4; nt++) mma_f16(c[mt][nt], af[mt], bf[nt]);
        }
        __syncthreads();
    }

#pragma unroll
    for (int mt = 0; mt < 4; mt++)
#pragma unroll
        for (int h = 0; h < 2; h++) {
            int o = wr * 64 + mt * 16 + h * 8 + (lane >> 2);
            float inv = gamma[o] * rsqrtf(var[o] + 1e-5f);
            float mb = mean[o], beta_ = beta[o], btv = bt[o];
#pragma unroll
            for (int nt = 0; nt < 4; nt++) {
                int mm = m0 + wc * 32 + nt * 8 + (lane & 3) * 2;
                size_t idx = ((size_t)b * CC + o) * NN + mm;
                float2 xv = *reinterpret_cast<const float2*>(&x[idx]);
                float y0 = (c[mt][nt][h * 2 + 0] + btv - mb) * inv + beta_;
                float y1 = (c[mt][nt][h * 2 + 1] + btv - mb) * inv + beta_;
                float2 o2;
                o2.x = xv.x + fmaxf(y0, 0.f);
                o2.y = xv.y + fmaxf(y1, 0.f);
                *reinterpret_cast<float2*>(&out[idx]) = o2;
            }
        }
#undef BF2F_LO
#undef BF2F_HI
#undef XR_ELOAD
#undef XR_PSTORE
}

// -------------------------------- launcher -----------------------------------------
extern "C" void kernel_launch(void* const* d_in, const int* in_sizes, int n_in,
                              void* d_out, int out_size)
{
    const float* x    = (const float*)d_in[0];
    const int*   disc = (const int*)d_in[1];
    // d_in[2] = xyz (unused by the reference)
    const float* Wq   = (const float*)d_in[3];
    const float* Wk   = (const float*)d_in[4];
    const float* Wv   = (const float*)d_in[5];
    const float* bv   = (const float*)d_in[6];
    const float* xlt  = (const float*)d_in[7];
    const float* ylt  = (const float*)d_in[8];
    const float* zlt  = (const float*)d_in[9];
    const float* Wt   = (const float*)d_in[10];
    const float* bt   = (const float*)d_in[11];
    const float* gamma= (const float*)d_in[12];
    const float* beta = (const float*)d_in[13];
    const float* mean = (const float*)d_in[14];
    const float* var  = (const float*)d_in[15];
    float* out = (float*)d_out;

    float *rowsuminv;
    __half *q, *k, *vh;
    __nv_bfloat16* energy;
    cudaGetSymbolAddress((void**)&q, g_q);
    cudaGetSymbolAddress((void**)&k, g_k);
    cudaGetSymbolAddress((void**)&vh, g_vh);
    cudaGetSymbolAddress((void**)&energy, g_energy);
    cudaGetSymbolAddress((void**)&rowsuminv, g_rowsuminv);

    const int smem_energy = (64 * 36 + 128 * 36) * 4 + 64 * 100 * 4 + (192 + 384 + 256) * 4;
    cudaFuncSetAttribute(energy2_kernel, cudaFuncAttributeMaxDynamicSharedMemorySize, smem_energy);
    cudaFuncSetAttribute(xrf_kernel, cudaFuncAttributeMaxDynamicSharedMemorySize, SMEM_XRF);

    // fused projections (q, k fp16 + vh fp16)
    projqkv_f16_kernel<<<dim3(NN / 128, 1, BB), 256>>>(Wq, Wk, Wv, x, bv, q, k, vh);

    // energy pass: fp16 MMA; stores bf16 exp(e) + fp32 rowsuminv
    energy2_kernel<<<dim3(NN / 64, BB), 256, smem_energy>>>(q, k, xlt, ylt, zlt, disc,
                                                            energy, rowsuminv);

    // fused: softmax-renorm + colsum + V@P + (x - ..) + Wt GEMM + BN + relu + residual
    xrf_kernel<<<dim3(NN / 128, 1, BB), 512, SMEM_XRF>>>(vh, energy, rowsuminv, x,
                                                         Wt, bt, gamma, beta, mean, var, out);
}

// round 16
// speedup vs baseline: 1.1110x; 1.1110x over previous
#include <cuda_runtime.h>
#include <cuda_fp16.h>
#include <cuda_bf16.h>
#include <math.h>

#define BB   16
#define CC   256
#define NN   2048
#define DQKD 64
#define BINS 32

// ---------------- scratch (device globals; no allocation allowed) ----------------
__device__ __half g_q[BB * NN * DQKD];            // [b][n][64] fp16 point-major
__device__ __half g_k[BB * NN * DQKD];            // [b][m][64] fp16 point-major
__device__ __half g_vh[BB * CC * NN];             // [b][c][n] fp16 V
__device__ __nv_bfloat16 g_energy[(size_t)BB * NN * NN]; // [b][n][m] exp(e) bf16
__device__ float  g_rowsuminv[BB * NN];
__device__ __half g_xdh[BB * CC * NN];            // x - x_r (fp16)

// ---------------- mma helpers ----------------
__device__ __forceinline__ unsigned packh2(float a, float b)
{
    __half2 h = __floats2half2_rn(a, b);
    return *reinterpret_cast<unsigned*>(&h);
}

__device__ __forceinline__ void mma_f16(float c[4], const unsigned a[4], const unsigned b[2])
{
    asm volatile(
        "mma.sync.aligned.m16n8k16.row.col.f32.f16.f16.f32 "
        "{%0,%1,%2,%3},{%4,%5,%6,%7},{%8,%9},{%0,%1,%2,%3};"
        : "+f"(c[0]), "+f"(c[1]), "+f"(c[2]), "+f"(c[3])
        : "r"(a[0]), "r"(a[1]), "r"(a[2]), "r"(a[3]), "r"(b[0]), "r"(b[1]));
}

__device__ __forceinline__ void ldsm_x4(unsigned r[4], const void* p)
{
    unsigned addr = (unsigned)__cvta_generic_to_shared(p);
    asm volatile("ldmatrix.sync.aligned.m8n8.x4.shared.b16 {%0,%1,%2,%3}, [%4];"
                 : "=r"(r[0]), "=r"(r[1]), "=r"(r[2]), "=r"(r[3]) : "r"(addr));
}

__device__ __forceinline__ void cp_async16(void* smem_dst, const void* gptr)
{
    unsigned dst = (unsigned)__cvta_generic_to_shared(smem_dst);
    asm volatile("cp.async.cg.shared.global [%0], [%1], 16;" :: "r"(dst), "l"(gptr));
}

// ============ shared fp16 128x128 GEMM body (A[o][k] row-major fp32, B=x [k][m]) ====
#define GEMM128_LOADA(Wrow_expr)                                                   \
    _Pragma("unroll")                                                              \
    for (int i = 0; i < 4; i++) {                                                  \
        int idx = t + i * 256;                                                     \
        int dd = idx >> 3, kq = idx & 7;                                           \
        const float* srcA = (Wrow_expr);                                           \
        float4 f = *reinterpret_cast<const float4*>(&srcA[k0 + kq * 4]);           \
        As[dd][kq * 2 + 0] = packh2(f.x, f.y);                                     \
        As[dd][kq * 2 + 1] = packh2(f.z, f.w);                                     \
    }

#define GEMM128_LOADB(xb)                                                          \
    _Pragma("unroll")                                                              \
    for (int i = 0; i < 2; i++) {                                                  \
        int task = t + i * 256;                                                    \
        int kp = task >> 5, m4 = task & 31;                                        \
        float4 f0 = *reinterpret_cast<const float4*>(&(xb)[(size_t)(k0 + 2 * kp) * NN + m0 + m4 * 4]); \
        float4 f1 = *reinterpret_cast<const float4*>(&(xb)[(size_t)(k0 + 2 * kp + 1) * NN + m0 + m4 * 4]); \
        Bs[kp][m4 * 4 + 0] = packh2(f0.x, f1.x);                                   \
        Bs[kp][m4 * 4 + 1] = packh2(f0.y, f1.y);                                   \
        Bs[kp][m4 * 4 + 2] = packh2(f0.z, f1.z);                                   \
        Bs[kp][m4 * 4 + 3] = packh2(f0.w, f1.w);                                   \
    }

#define GEMM128_MMA()                                                              \
    _Pragma("unroll")                                                              \
    for (int ks = 0; ks < 2; ks++) {                                               \
        unsigned af[4][4], bf[4][2];                                               \
        _Pragma("unroll")                                                          \
        for (int mt = 0; mt < 4; mt++) {                                           \
            int row = wm * 64 + mt * 16 + (lane >> 2);                             \
            int col = ks * 8 + (lane & 3);                                         \
            af[mt][0] = As[row][col];                                              \
            af[mt][1] = As[row + 8][col];                                          \
            af[mt][2] = As[row][col + 4];                                          \
            af[mt][3] = As[row + 8][col + 4];                                      \
        }                                                                          \
        _Pragma("unroll")                                                          \
        for (int nt = 0; nt < 4; nt++) {                                           \
            int kp = ks * 8 + (lane & 3);                                          \
            int cm = wn * 32 + nt * 8 + (lane >> 2);                               \
            bf[nt][0] = Bs[kp][cm];                                                \
            bf[nt][1] = Bs[kp + 4][cm];                                            \
        }                                                                          \
        _Pragma("unroll")                                                          \
        for (int mt = 0; mt < 4; mt++)                                             \
            _Pragma("unroll")                                                      \
            for (int nt = 0; nt < 4; nt++) mma_f16(c[mt][nt], af[mt], bf[nt]);     \
    }

// ---------------- K1qk: [q;k] = [Wq;Wk] @ x  (fp16 MMA; writes fp16) ---------------
__global__ __launch_bounds__(256) void projqk_f16_kernel(
    const float* __restrict__ Wq, const float* __restrict__ Wk,
    const float* __restrict__ x, __half* __restrict__ qo, __half* __restrict__ ko)
{
    __shared__ unsigned As[128][20];
    __shared__ unsigned Bs[16][136];
    int b  = blockIdx.z;
    int m0 = blockIdx.x * 128;
    int t  = threadIdx.x;
    int warp = t >> 5, lane = t & 31;
    int wm = warp >> 2, wn = warp & 3;
    float c[4][4][4] = {};
    const float* xb = x + (size_t)b * CC * NN;

    for (int k0 = 0; k0 < CC; k0 += 32) {
        GEMM128_LOADA((((t + i * 256) >> 3) < 64) ? (Wq + (size_t)((t + i * 256) >> 3) * CC)
                                                  : (Wk + (size_t)(((t + i * 256) >> 3) - 64) * CC))
        GEMM128_LOADB(xb)
        __syncthreads();
        GEMM128_MMA()
        __syncthreads();
    }
#pragma unroll
    for (int mt = 0; mt < 4; mt++)
#pragma unroll
        for (int h = 0; h < 2; h++) {
            int o = wm * 64 + mt * 16 + h * 8 + (lane >> 2);
            __half* dst = (o < 64) ? qo : ko;
            int oc = o & 63;
#pragma unroll
            for (int nt = 0; nt < 4; nt++) {
                int n = m0 + wn * 32 + nt * 8 + (lane & 3) * 2;
                dst[((size_t)b * NN + n) * 64 + oc]     = __float2half_rn(c[mt][nt][h * 2 + 0]);
                dst[((size_t)b * NN + n + 1) * 64 + oc] = __float2half_rn(c[mt][nt][h * 2 + 1]);
            }
        }
}

// ---------------- K1v: vh = fp16(Wv @ x + bv) (fp16 MMA) ----------------
__global__ __launch_bounds__(256) void proj_v_f16_kernel(
    const float* __restrict__ Wv, const float* __restrict__ x,
    const float* __restrict__ bv, __half* __restrict__ out)
{
    __shared__ unsigned As[128][20];
    __shared__ unsigned Bs[16][136];
    int b  = blockIdx.z;
    int m0 = blockIdx.x * 128;
    int o0 = blockIdx.y * 128;
    int t  = threadIdx.x;
    int warp = t >> 5, lane = t & 31;
    int wm = warp >> 2, wn = warp & 3;
    float c[4][4][4] = {};
    const float* xb = x + (size_t)b * CC * NN;

    for (int k0 = 0; k0 < CC; k0 += 32) {
        GEMM128_LOADA(Wv + (size_t)(o0 + ((t + i * 256) >> 3)) * CC)
        GEMM128_LOADB(xb)
        __syncthreads();
        GEMM128_MMA()
        __syncthreads();
    }
#pragma unroll
    for (int mt = 0; mt < 4; mt++)
#pragma unroll
        for (int h = 0; h < 2; h++) {
            int o = o0 + wm * 64 + mt * 16 + h * 8 + (lane >> 2);
            float bvv = bv[o];
#pragma unroll
            for (int nt = 0; nt < 4; nt++) {
                int mm = m0 + wn * 32 + nt * 8 + (lane & 3) * 2;
                size_t idx = ((size_t)b * CC + o) * NN + mm;
                __half2 h2 = __floats2half2_rn(c[mt][nt][h * 2 + 0] + bvv,
                                               c[mt][nt][h * 2 + 1] + bvv);
                *reinterpret_cast<__half2*>(&out[idx]) = h2;
            }
        }
}

// ---------------- K6: out = x + relu(BN(Wt @ xd + bt))  (fp16 MMA, fp16 xd) --------
__global__ __launch_bounds__(256) void final_f16_kernel(
    const float* __restrict__ Wt, const __half* __restrict__ xdin,
    const float* __restrict__ bt, const float* __restrict__ gamma,
    const float* __restrict__ beta, const float* __restrict__ mean,
    const float* __restrict__ var, const float* __restrict__ x,
    float* __restrict__ out)
{
    __shared__ unsigned As[128][20];
    __shared__ unsigned Bs[16][136];
    int b  = blockIdx.z;
    int m0 = blockIdx.x * 128;
    int o0 = blockIdx.y * 128;
    int t  = threadIdx.x;
    int warp = t >> 5, lane = t & 31;
    int wm = warp >> 2, wn = warp & 3;
    float c[4][4][4] = {};
    const __half* xb = xdin + (size_t)b * CC * NN;

    for (int k0 = 0; k0 < CC; k0 += 32) {
        GEMM128_LOADA(Wt + (size_t)(o0 + ((t + i * 256) >> 3)) * CC)
        // B: fp16 xd rows 2kp, 2kp+1 -> k-pair interleave via byte_perm
        {
            int kp = t >> 4, mq = t & 15;   // 16 kp x 16 groups of 8 m = 256 tasks
            uint4 ra = *reinterpret_cast<const uint4*>(&xb[(size_t)(k0 + 2 * kp) * NN + m0 + mq * 8]);
            uint4 rb = *reinterpret_cast<const uint4*>(&xb[(size_t)(k0 + 2 * kp + 1) * NN + m0 + mq * 8]);
            const unsigned* wa = &ra.x;
            const unsigned* wb = &rb.x;
#pragma unroll
            for (int w = 0; w < 4; w++) {
                Bs[kp][mq * 8 + 2 * w + 0] = __byte_perm(wa[w], wb[w], 0x5410);
                Bs[kp][mq * 8 + 2 * w + 1] = __byte_perm(wa[w], wb[w], 0x7632);
            }
        }
        __syncthreads();
        GEMM128_MMA()
        __syncthreads();
    }
#pragma unroll
    for (int mt = 0; mt < 4; mt++)
#pragma unroll
        for (int h = 0; h < 2; h++) {
            int o = o0 + wm * 64 + mt * 16 + h * 8 + (lane >> 2);
            float inv = gamma[o] * rsqrtf(var[o] + 1e-5f);
            float mb = mean[o], beta_ = beta[o], btv = bt[o];
#pragma unroll
            for (int nt = 0; nt < 4; nt++) {
                int mm = m0 + wn * 32 + nt * 8 + (lane & 3) * 2;
                size_t idx = ((size_t)b * CC + o) * NN + mm;
                float2 xv = *reinterpret_cast<const float2*>(&x[idx]);
                float y0 = (c[mt][nt][h * 2 + 0] + btv - mb) * inv + beta_;
                float y1 = (c[mt][nt][h * 2 + 1] + btv - mb) * inv + beta_;
                float2 o2;
                o2.x = xv.x + fmaxf(y0, 0.f);
                o2.y = xv.y + fmaxf(y1, 0.f);
                *reinterpret_cast<float2*>(&out[idx]) = o2;
            }
        }
}

// ---------------- K3: energy pass (fp16 MMA, fp16 q/k, ldmatrix A) ------------------
__global__ __launch_bounds__(256, 2) void energy2_kernel(
    const __half* __restrict__ q, const __half* __restrict__ k,
    const float* __restrict__ xlt, const float* __restrict__ ylt,
    const float* __restrict__ zlt, const int* __restrict__ disc,
    __nv_bfloat16* __restrict__ energy, float* __restrict__ rowsuminv)
{
    extern __shared__ unsigned smu[];
    unsigned* Qe = smu;                     // [64][36] u32 (half pairs)
    unsigned* Ks = Qe + 64 * 36;            // [128][36] u32 (half pairs; lt overlay)
    float*    Tw = (float*)(Ks + 128 * 36); // [64][100]
    int*      dn = (int*)(Tw + 64 * 100);   // [192]
    int*      dm = dn + 192;                // [384]
    float*    red = (float*)(dm + 384);     // [256]

    int b  = blockIdx.y;
    int n0 = blockIdx.x * 64;
    int t  = threadIdx.x;
    int warp = t >> 5, lane = t & 31;
    int wr = warp >> 2, wc = warp & 3;

    int lm_row = ((lane >> 3) & 1) * 8 + (lane & 7);
    int lm_k   = (lane >> 4) * 8;

#pragma unroll
    for (int i = 0; i < 2; i++) {
        int idx = t + i * 256;
        int n = idx >> 3, kq = idx & 7;
        uint4 u = *reinterpret_cast<const uint4*>(&q[((size_t)b * NN + n0 + n) * 64 + kq * 8]);
        Qe[n * 36 + kq * 4 + 0] = u.x; Qe[n * 36 + kq * 4 + 1] = u.y;
        Qe[n * 36 + kq * 4 + 2] = u.z; Qe[n * 36 + kq * 4 + 3] = u.w;
    }
    if (t < 192) dn[t] = disc[((size_t)b * NN + n0) * 3 + t];

    uint4 kreg[4];
    int dmreg0, dmreg1;
#pragma unroll
    for (int i = 0; i < 4; i++) {
        int idx = t + i * 256;
        int m = idx >> 3, kq = idx & 7;
        kreg[i] = *reinterpret_cast<const uint4*>(&k[((size_t)b * NN + m) * 64 + kq * 8]);
    }
    dmreg0 = disc[((size_t)b * NN) * 3 + t];
    dmreg1 = (t < 128) ? disc[((size_t)b * NN) * 3 + t + 256] : 0;

    const float* lt_ptrs[3] = {xlt, ylt, zlt};
    unsigned* lts = Ks;
    int qrow0 = (warp & 3) * 16;
    int qcol0 = (warp >> 2) * 32;
    for (int a = 0; a < 3; a++) {
        __syncthreads();
        for (int i = t; i < 64 * 32; i += 256) {
            int r = i >> 5, jp = i & 31;
            float v0 = (r < 63) ? lt_ptrs[a][r * 64 + 2 * jp] : 0.f;
            float v1 = (r < 63) ? lt_ptrs[a][r * 64 + 2 * jp + 1] : 0.f;
            lts[r * 36 + jp] = packh2(v0, v1);
        }
        __syncthreads();
        float c2[4][4] = {};
#pragma unroll
        for (int ks = 0; ks < 4; ks++) {
            unsigned af[4], bf[4][2];
            ldsm_x4(af, (const unsigned short*)Qe + (qrow0 + lm_row) * 72 + ks * 16 + lm_k);
            int col = ks * 8 + (lane & 3);
#pragma unroll
            for (int nt = 0; nt < 4; nt++) {
                int cm = qcol0 + nt * 8 + (lane >> 2);
                bf[nt][0] = lts[cm * 36 + col];
                bf[nt][1] = lts[cm * 36 + col + 4];
            }
#pragma unroll
            for (int nt = 0; nt < 4; nt++) mma_f16(c2[nt], af, bf[nt]);
        }
#pragma unroll
        for (int nt = 0; nt < 4; nt++)
#pragma unroll
            for (int h = 0; h < 2; h++) {
                int row = qrow0 + h * 8 + (lane >> 2);
                int dna = dn[row * 3 + a];
#pragma unroll
                for (int j = 0; j < 2; j++) {
                    int col = qcol0 + nt * 8 + (lane & 3) * 2 + j;
                    int d = col - 31 + dna;
                    if (d >= 0 && d < 32)
                        Tw[row * 100 + a * 32 + d] = c2[nt][h * 2 + j];
                }
            }
    }

    float rsm[2][2] = {};

    for (int m0c = 0; m0c < NN; m0c += 128) {
        __syncthreads();
#pragma unroll
        for (int i = 0; i < 4; i++) {
            int idx = t + i * 256;
            int m = idx >> 3, kq = idx & 7;
            Ks[m * 36 + kq * 4 + 0] = kreg[i].x; Ks[m * 36 + kq * 4 + 1] = kreg[i].y;
            Ks[m * 36 + kq * 4 + 2] = kreg[i].z; Ks[m * 36 + kq * 4 + 3] = kreg[i].w;
        }
        dm[t] = dmreg0;
        if (t < 128) dm[t + 256] = dmreg1;
        __syncthreads();
        if (m0c + 128 < NN) {
#pragma unroll
            for (int i = 0; i < 4; i++) {
                int idx = t + i * 256;
                int m = idx >> 3, kq = idx & 7;
                kreg[i] = *reinterpret_cast<const uint4*>(
                    &k[((size_t)b * NN + m0c + 128 + m) * 64 + kq * 8]);
            }
            dmreg0 = disc[((size_t)b * NN + m0c + 128) * 3 + t];
            dmreg1 = (t < 128) ? disc[((size_t)b * NN + m0c + 128) * 3 + t + 256] : 0;
        }

        float c[2][4][4] = {};
#pragma unroll
        for (int ks = 0; ks < 4; ks++) {
            unsigned af[2][4], bf[4][2];
#pragma unroll
            for (int mt = 0; mt < 2; mt++)
                ldsm_x4(af[mt], (const unsigned short*)Qe
                        + (wr * 32 + mt * 16 + lm_row) * 72 + ks * 16 + lm_k);
            int col = ks * 8 + (lane & 3);
#pragma unroll
            for (int nt = 0; nt < 4; nt++) {
                int cm = wc * 32 + nt * 8 + (lane >> 2);
                bf[nt][0] = Ks[cm * 36 + col];
                bf[nt][1] = Ks[cm * 36 + col + 4];
            }
#pragma unroll
            for (int mt = 0; mt < 2; mt++)
#pragma unroll
                for (int nt = 0; nt < 4; nt++) mma_f16(c[mt][nt], af[mt], bf[nt]);
        }

#pragma unroll
        for (int mt = 0; mt < 2; mt++)
#pragma unroll
            for (int h = 0; h < 2; h++) {
                int row_l = wr * 32 + mt * 16 + h * 8 + (lane >> 2);
                const float* twr = &Tw[row_l * 100];
#pragma unroll
                for (int nt = 0; nt < 4; nt++) {
                    float pv[2];
#pragma unroll
                    for (int j = 0; j < 2; j++) {
                        int col = wc * 32 + nt * 8 + (lane & 3) * 2 + j;
                        float e = c[mt][nt][h * 2 + j]
                                + twr[dm[col * 3 + 0]]
                                + twr[32 + dm[col * 3 + 1]]
                                + twr[64 + dm[col * 3 + 2]];
                        float p = __expf(e);
                        rsm[mt][h] += p;
                        pv[j] = p;
                    }
                    int col0 = wc * 32 + nt * 8 + (lane & 3) * 2;
                    __nv_bfloat162 bp = __floats2bfloat162_rn(pv[0], pv[1]);
                    *reinterpret_cast<__nv_bfloat162*>(
                        &energy[((size_t)b * NN + n0 + row_l) * NN + m0c + col0]) = bp;
                }
            }
    }

#pragma unroll
    for (int mt = 0; mt < 2; mt++)
#pragma unroll
        for (int h = 0; h < 2; h++) {
            float s = rsm[mt][h];
            s += __shfl_xor_sync(0xffffffffu, s, 1);
            s += __shfl_xor_sync(0xffffffffu, s, 2);
            if ((lane & 3) == 0) {
                int row_l = wr * 32 + mt * 16 + h * 8 + (lane >> 2);
                red[wc * 64 + row_l] = s;
            }
        }
    __syncthreads();
    if (t < 64) {
        float s = red[t] + red[64 + t] + red[128 + t] + red[192 + t];
        rowsuminv[b * NN + n0 + t] = 1.f / s;
    }
}

// ---------------- K5: xd = x - (V @ P) / colsum  (fp16 MMA, pipelined, ldmatrix) ----
#define VSTRIDE_H 72   // halves per V row (64 data + 8 pad; 144B stride, conflict-free)
#define PSTRIDE   132  // u32 (half2) per P kp-row
__global__ __launch_bounds__(512) void xr512_kernel(
    const __half* __restrict__ vh, const __nv_bfloat16* __restrict__ energy,
    const float* __restrict__ rowsuminv, const float* __restrict__ x,
    __half* __restrict__ xdh)
{
    extern __shared__ char smc[];
    __half* Vh = (__half*)smc;                                   // 2 x 256*VSTRIDE_H halves
    unsigned* Pb = (unsigned*)(smc + 2 * 256 * VSTRIDE_H * 2);   // 2 x 32*PSTRIDE u32
    float* csp = (float*)(smc + 2 * 256 * VSTRIDE_H * 2 + 2 * 32 * PSTRIDE * 4); // [512][8]
    float* cscale = csp + 512 * 8;                               // [128]

    int b  = blockIdx.z;
    int m0 = blockIdx.x * 128;
    int t  = threadIdx.x;
    int warp = t >> 5, lane = t & 31;
    int wr = warp >> 2, wc = warp & 3;
    float c[4][4][4] = {};
    float csum[8] = {};
    const __half* vb = vh + (size_t)b * CC * NN;
    const __nv_bfloat16* eb = energy + (size_t)b * NN * NN;
    const float* ri = rowsuminv + b * NN;

    int kp_t = t >> 4;        // 0..31 : P kp row
    int mq8  = t & 15;        // m group of 8 columns
    int lm_row = ((lane >> 3) & 1) * 8 + (lane & 7);
    int lm_k   = (lane >> 4) * 8;

#define BF2F_LO(u) __uint_as_float((u) << 16)
#define BF2F_HI(u) __uint_as_float((u) & 0xffff0000u)

#define XR_ELOAD(kb)                                                                \
    r0 = *reinterpret_cast<const uint4*>(&eb[(size_t)((kb) + 2 * kp_t) * NN + m0 + mq8 * 8]); \
    r1 = *reinterpret_cast<const uint4*>(&eb[(size_t)((kb) + 2 * kp_t + 1) * NN + m0 + mq8 * 8]); \
    rv0 = ri[(kb) + 2 * kp_t]; rv1 = ri[(kb) + 2 * kp_t + 1];

#define XR_PSTORE(Pdst)                                                             \
    do {                                                                            \
        unsigned* pd = &(Pdst)[kp_t * PSTRIDE + mq8 * 8];                           \
        const unsigned* w0 = &r0.x; const unsigned* w1 = &r1.x;                     \
        _Pragma("unroll")                                                           \
        for (int w = 0; w < 4; w++) {                                               \
            float a0 = BF2F_LO(w0[w]) * rv0, a1 = BF2F_HI(w0[w]) * rv0;             \
            float b0 = BF2F_LO(w1[w]) * rv1, b1 = BF2F_HI(w1[w]) * rv1;             \
            csum[2 * w + 0] += a0 + b0;                                             \
            csum[2 * w + 1] += a1 + b1;                                             \
            pd[2 * w + 0] = packh2(a0, b0);                                         \
            pd[2 * w + 1] = packh2(a1, b1);                                         \
        }                                                                           \
    } while (0)

    // ---- prologue: chunk 0 ----
    {
        uint4 r0, r1; float rv0, rv1;
#pragma unroll
        for (int i = 0; i < 4; i++) {
            int idx = t + i * 512;
            int dd = idx >> 3, kq = idx & 7;
            cp_async16(&Vh[dd * VSTRIDE_H + kq * 8], &vb[(size_t)dd * NN + kq * 8]);
        }
        asm volatile("cp.async.commit_group;");
        XR_ELOAD(0);
        XR_PSTORE(Pb);
        asm volatile("cp.async.wait_group 0;");
        __syncthreads();
    }

    int cur = 0;
    for (int k0 = 0; k0 < NN; k0 += 64) {
        int nxt = cur ^ 1;
        bool has_next = (k0 + 64) < NN;
        uint4 r0, r1; float rv0, rv1;
        if (has_next) {
            __half* Vn = Vh + nxt * 256 * VSTRIDE_H;
#pragma unroll
            for (int i = 0; i < 4; i++) {
                int idx = t + i * 512;
                int dd = idx >> 3, kq = idx & 7;
                cp_async16(&Vn[dd * VSTRIDE_H + kq * 8], &vb[(size_t)dd * NN + k0 + 64 + kq * 8]);
            }
            asm volatile("cp.async.commit_group;");
            XR_ELOAD(k0 + 64);     // issue E loads BEFORE the MMA phase
        }
        const __half* Vcur = Vh + cur * 256 * VSTRIDE_H;
        const unsigned* Ps = Pb + cur * 32 * PSTRIDE;
#pragma unroll
        for (int ks16 = 0; ks16 < 4; ks16++) {
            unsigned af[4][4], bf[4][2];
#pragma unroll
            for (int mt = 0; mt < 4; mt++)
                ldsm_x4(af[mt], Vcur + (wr * 64 + mt * 16 + lm_row) * VSTRIDE_H
                                + ks16 * 16 + lm_k);
#pragma unroll
            for (int nt = 0; nt < 4; nt++) {
                int cm = wc * 32 + nt * 8 + (lane >> 2);
                int kp = ks16 * 8 + (lane & 3);
                bf[nt][0] = Ps[kp * PSTRIDE + cm];
                bf[nt][1] = Ps[(kp + 4) * PSTRIDE + cm];
            }
#pragma unroll
            for (int mt = 0; mt < 4; mt++)
#pragma unroll
                for (int nt = 0; nt < 4; nt++) mma_f16(c[mt][nt], af[mt], bf[nt]);
        }
        if (has_next) {
            XR_PSTORE(Pb + nxt * 32 * PSTRIDE);
            asm volatile("cp.async.wait_group 0;");
        }
        __syncthreads();
        cur = nxt;
    }

    // colsum reduce: thread t owned columns mq8*8 .. +7
#pragma unroll
    for (int j = 0; j < 8; j++) csp[t * 8 + j] = csum[j];
    __syncthreads();
    if (t < 128) {
        int g = t >> 3, j = t & 7;
        float s = 0.f;
#pragma unroll
        for (int kp = 0; kp < 32; kp++) s += csp[(kp * 16 + g) * 8 + j];
        cscale[t] = 1.f / (1e-9f + s);
    }
    __syncthreads();

#pragma unroll
    for (int mt = 0; mt < 4; mt++)
#pragma unroll
        for (int h = 0; h < 2; h++) {
            int dd = wr * 64 + mt * 16 + h * 8 + (lane >> 2);
#pragma unroll
            for (int nt = 0; nt < 4; nt++) {
                int mloc = wc * 32 + nt * 8 + (lane & 3) * 2;
                float s0 = cscale[mloc], s1 = cscale[mloc + 1];
                size_t idx = ((size_t)b * CC + dd) * NN + m0 + mloc;
                float2 xv = *reinterpret_cast<const float2*>(&x[idx]);
                __half2 o2 = __floats2half2_rn(xv.x - c[mt][nt][h * 2 + 0] * s0,
                                               xv.y - c[mt][nt][h * 2 + 1] * s1);
                *reinterpret_cast<__half2*>(&xdh[idx]) = o2;
            }
        }
#undef BF2F_LO
#undef BF2F_HI
#undef XR_ELOAD
#undef XR_PSTORE
}

// -------------------------------- launcher -----------------------------------------
extern "C" void kernel_launch(void* const* d_in, const int* in_sizes, int n_in,
                              void* d_out, int out_size)
{
    const float* x    = (const float*)d_in[0];
    const int*   disc = (const int*)d_in[1];
    // d_in[2] = xyz (unused by the reference)
    const float* Wq   = (const float*)d_in[3];
    const float* Wk   = (const float*)d_in[4];
    const float* Wv   = (const float*)d_in[5];
    const float* bv   = (const float*)d_in[6];
    const float* xlt  = (const float*)d_in[7];
    const float* ylt  = (const float*)d_in[8];
    const float* zlt  = (const float*)d_in[9];
    const float* Wt   = (const float*)d_in[10];
    const float* bt   = (const float*)d_in[11];
    const float* gamma= (const float*)d_in[12];
    const float* beta = (const float*)d_in[13];
    const float* mean = (const float*)d_in[14];
    const float* var  = (const float*)d_in[15];
    float* out = (float*)d_out;

    float *rowsuminv;
    __half *q, *k, *vh, *xdh;
    __nv_bfloat16* energy;
    cudaGetSymbolAddress((void**)&q, g_q);
    cudaGetSymbolAddress((void**)&k, g_k);
    cudaGetSymbolAddress((void**)&vh, g_vh);
    cudaGetSymbolAddress((void**)&energy, g_energy);
    cudaGetSymbolAddress((void**)&rowsuminv, g_rowsuminv);
    cudaGetSymbolAddress((void**)&xdh, g_xdh);

    const int smem_energy = (64 * 36 + 128 * 36) * 4 + 64 * 100 * 4 + (192 + 384 + 256) * 4;
    const int smem_xr = 2 * 256 * VSTRIDE_H * 2 + 2 * 32 * PSTRIDE * 4 + (512 * 8 + 128) * 4;
    cudaFuncSetAttribute(energy2_kernel, cudaFuncAttributeMaxDynamicSharedMemorySize, smem_energy);
    cudaFuncSetAttribute(xr512_kernel, cudaFuncAttributeMaxDynamicSharedMemorySize, smem_xr);

    // projections (fp16 MMA; q/k stored fp16)
    projqk_f16_kernel<<<dim3(NN / 128, 1, BB), 256>>>(Wq, Wk, x, q, k);
    proj_v_f16_kernel<<<dim3(NN / 128, CC / 128, BB), 256>>>(Wv, x, bv, vh);

    // energy pass: fp16 MMA; stores bf16 exp(e) + fp32 rowsuminv
    energy2_kernel<<<dim3(NN / 64, BB), 256, smem_energy>>>(q, k, xlt, ylt, zlt, disc,
                                                            energy, rowsuminv);

    // fused renorm + colsum + xd(fp16) = x - (V @ P) * colscale
    xr512_kernel<<<dim3(NN / 128, 1, BB), 512, smem_xr>>>(vh, energy, rowsuminv, x, xdh);

    // out = x + relu(BN(Wt @ xd + bt))  (fp16 MMA, fp16 xd)
    final_f16_kernel<<<dim3(NN / 128, CC / 128, BB), 256>>>(Wt, xdh, bt, gamma, beta, mean, var, x, out);
}